// round 16
// baseline (speedup 1.0000x reference)
#include <cuda_runtime.h>
#include <cuda_bf16.h>
#include <math.h>

#define BB 2048
#define VV 3129
#define DD 768
#define VP 3200              // V padded to 25*128
#define NPART 1024

#define BM 128
#define NBN (VP / BM)        // 25 blocks per dim
#define NBLK (NBN * (NBN + 1) / 2)   // 325 upper-triangle blocks
#define NCH 12               // K chunks of 64 elems (128B rows)
#define CHB 16384            // bytes per 128-row x 128B chunk tile
#define STAGE_BYTES (2 * CHB)        // A + B per stage
#define GRAM_SMEM (2 * STAGE_BYTES)  // 65536 B dynamic

#define ROWB (VP * 2)                // bytes per G row (6400)
#define AM_ROWS 4                    // rows staged per argmax block
#define AM_SMEM (AM_ROWS * ROWB + VP * 2)  // 32000 B -> 7 CTAs/SM

// Scratch (static device globals)
// g_Ep: chunk-major pre-swizzled bf16 E: [c][v][64], col16 ^= (v&7)
__device__ __nv_bfloat16 g_Ep[NCH * VP * 64];
__device__ __nv_bfloat16 g_G[VP * VP];     // Gram bf16 (diag zeroed, pad = 0)
__device__ float g_npart[NBN * VP];        // per-slot row partials of sum G^2
__device__ __nv_bfloat16 g_rinvh[VP];      // bf16 1/norm (0 for padded rows)
__device__ int   g_map[VV];
__device__ float g_p1[NPART];
__device__ float g_p2[NPART];

// ---------------------------------------------------------------------------
// PTX helpers (base sm_90+ features only)
// ---------------------------------------------------------------------------
__device__ __forceinline__ unsigned smem_u32(const void* p) {
    return (unsigned)__cvta_generic_to_shared(p);
}
__device__ __forceinline__ void mbar_init(unsigned a, unsigned cnt) {
    asm volatile("mbarrier.init.shared.b64 [%0], %1;" :: "r"(a), "r"(cnt) : "memory");
}
__device__ __forceinline__ void mbar_expect_tx(unsigned a, unsigned bytes) {
    asm volatile("mbarrier.arrive.expect_tx.shared.b64 _, [%0], %1;"
                 :: "r"(a), "r"(bytes) : "memory");
}
__device__ __forceinline__ void mbar_wait(unsigned a, unsigned parity) {
    unsigned done;
    asm volatile(
        "{\n\t.reg .pred p;\n\t"
        "mbarrier.try_wait.parity.shared.b64 p, [%1], %2;\n\t"
        "selp.b32 %0, 1, 0, p;\n\t}"
        : "=r"(done) : "r"(a), "r"(parity) : "memory");
    if (!done) {
        asm volatile(
            "{\n\t.reg .pred P1;\n\t"
            "WAIT_LOOP_%=:\n\t"
            "mbarrier.try_wait.parity.shared.b64 P1, [%0], %1, 0x989680;\n\t"
            "@P1 bra.uni WAIT_DONE_%=;\n\t"
            "bra.uni WAIT_LOOP_%=;\n\t"
            "WAIT_DONE_%=:\n\t}"
            :: "r"(a), "r"(parity) : "memory");
    }
}
__device__ __forceinline__ void bulk_ld(unsigned smem_dst, const void* gsrc,
                                        unsigned bytes, unsigned mbar) {
    asm volatile(
        "cp.async.bulk.shared::cluster.global.mbarrier::complete_tx::bytes "
        "[%0], [%1], %2, [%3];"
        :: "r"(smem_dst), "l"(gsrc), "r"(bytes), "r"(mbar) : "memory");
}
__device__ __forceinline__ void mma16816(float& c0, float& c1, float& c2, float& c3,
                                         unsigned a0, unsigned a1, unsigned a2, unsigned a3,
                                         unsigned b0, unsigned b1) {
    asm volatile(
        "mma.sync.aligned.m16n8k16.row.col.f32.bf16.bf16.f32 "
        "{%0,%1,%2,%3}, {%4,%5,%6,%7}, {%8,%9}, {%0,%1,%2,%3};\n"
        : "+f"(c0), "+f"(c1), "+f"(c2), "+f"(c3)
        : "r"(a0), "r"(a1), "r"(a2), "r"(a3), "r"(b0), "r"(b1));
}
__device__ __forceinline__ void ldsm_x4(unsigned& r0, unsigned& r1,
                                        unsigned& r2, unsigned& r3, unsigned addr) {
    asm volatile("ldmatrix.sync.aligned.m8n8.x4.shared.b16 {%0,%1,%2,%3}, [%4];\n"
                 : "=r"(r0), "=r"(r1), "=r"(r2), "=r"(r3) : "r"(addr));
}

// ---------------------------------------------------------------------------
// Kernel 0: E fp32 -> bf16, chunk-major pre-swizzled layout; pad rows zero.
// ---------------------------------------------------------------------------
__global__ void convert_kernel(const float* __restrict__ E) {
    int idx = blockIdx.x * blockDim.x + threadIdx.x;    // over VP * 96
    if (idx >= VP * 96) return;
    int v = idx / 96, g = idx % 96;                     // g: 16B group in row
    int c = g >> 3, c16 = g & 7;
    int sw = c16 ^ (v & 7);
    uint4 pk = make_uint4(0u, 0u, 0u, 0u);
    if (v < VV) {
        const float4* src = (const float4*)&E[(size_t)v * DD + g * 8];
        float4 f0 = src[0], f1 = src[1];
        __nv_bfloat162 h0 = __floats2bfloat162_rn(f0.x, f0.y);
        __nv_bfloat162 h1 = __floats2bfloat162_rn(f0.z, f0.w);
        __nv_bfloat162 h2 = __floats2bfloat162_rn(f1.x, f1.y);
        __nv_bfloat162 h3 = __floats2bfloat162_rn(f1.z, f1.w);
        pk.x = *(unsigned*)&h0; pk.y = *(unsigned*)&h1;
        pk.z = *(unsigned*)&h2; pk.w = *(unsigned*)&h3;
    }
    *(uint4*)&g_Ep[((size_t)c * VP + v) * 64 + sw * 8] = pk;
}

// ---------------------------------------------------------------------------
// Kernel 1: symmetric Gram (R10/R13-proven: 2-stage cp.async.bulk + mma.sync).
// ---------------------------------------------------------------------------
__global__ __launch_bounds__(256, 2) void gram_kernel() {
    extern __shared__ __align__(128) unsigned char dyn[];
    __shared__ __align__(8) unsigned long long mbar[2];
    __shared__ float nspart[BM][4];
    __shared__ float cspart[BM][2];

    int by = 0, rem = blockIdx.x;
    while (rem >= NBN - by) { rem -= NBN - by; by++; }
    const int bx = by + rem;
    const int gm = by * BM;
    const int gn = bx * BM;

    const int t    = threadIdx.x;
    const int warp = t >> 5;
    const int lane = t & 31;
    const int qrow = lane >> 2;
    const int qcol = lane & 3;
    const int mwarp = warp >> 2;
    const int nwarp = warp & 3;
    const int m0   = mwarp * 64;
    const int n0   = nwarp * 32;

    const int lg8  = (lane >> 3) & 1;
    const int lg16 = lane >> 4;
    const int lr8  = lane & 7;

    const unsigned dynA = smem_u32(dyn);
    const unsigned mb0 = smem_u32(&mbar[0]);
    const unsigned mb1 = smem_u32(&mbar[1]);

    int aBase[4], bBase[2], swA[4], swB[4];
#pragma unroll
    for (int i = 0; i < 4; i++)
        aBase[i] = (m0 + i * 16 + lg8 * 8 + lr8) * 128;
#pragma unroll
    for (int p = 0; p < 2; p++)
        bBase[p] = (n0 + p * 16 + lg16 * 8 + lr8) * 128;
#pragma unroll
    for (int k16 = 0; k16 < 4; k16++) {
        swA[k16] = (((k16 * 2 + lg16) ^ lr8) << 4);
        swB[k16] = (((k16 * 2 + lg8) ^ lr8) << 4);
    }

    float acc[4][4][4];
#pragma unroll
    for (int i = 0; i < 4; i++)
#pragma unroll
        for (int j = 0; j < 4; j++)
#pragma unroll
            for (int c = 0; c < 4; c++) acc[i][j][c] = 0.f;

    if (t == 0) { mbar_init(mb0, 1); mbar_init(mb1, 1); }
    __syncthreads();

    auto issue = [&](int c) {
        unsigned full = (c & 1) ? mb1 : mb0;
        unsigned sA = dynA + (c & 1) * STAGE_BYTES;
        mbar_expect_tx(full, STAGE_BYTES);
        bulk_ld(sA,       &g_Ep[((size_t)c * VP + gm) * 64], CHB, full);
        bulk_ld(sA + CHB, &g_Ep[((size_t)c * VP + gn) * 64], CHB, full);
    };

    if (t == 0) { issue(0); issue(1); }

    for (int c = 0; c < NCH; c++) {
        const unsigned full = (c & 1) ? mb1 : mb0;
        mbar_wait(full, (c >> 1) & 1);

        const unsigned aB = dynA + (c & 1) * STAGE_BYTES;
        const unsigned bB = aB + CHB;
#pragma unroll
        for (int k16 = 0; k16 < 4; k16++) {
            unsigned af[4][4], bfr[4][2];
#pragma unroll
            for (int i = 0; i < 4; i++)
                ldsm_x4(af[i][0], af[i][1], af[i][2], af[i][3],
                        aB + aBase[i] + swA[k16]);
#pragma unroll
            for (int p = 0; p < 2; p++)
                ldsm_x4(bfr[2 * p][0], bfr[2 * p][1],
                        bfr[2 * p + 1][0], bfr[2 * p + 1][1],
                        bB + bBase[p] + swB[k16]);
#pragma unroll
            for (int i = 0; i < 4; i++)
#pragma unroll
                for (int j = 0; j < 4; j++)
                    mma16816(acc[i][j][0], acc[i][j][1], acc[i][j][2], acc[i][j][3],
                             af[i][0], af[i][1], af[i][2], af[i][3],
                             bfr[j][0], bfr[j][1]);
        }
        __syncthreads();
        if (t == 0 && c + 2 < NCH) issue(c + 2);
    }

    // --- row norm partials (slot bx, rows gm..gm+127) ---
#pragma unroll
    for (int i = 0; i < 4; i++) {
#pragma unroll
        for (int h = 0; h < 2; h++) {
            float s = 0.f;
#pragma unroll
            for (int j = 0; j < 4; j++) {
                float v0 = acc[i][j][2 * h + 0];
                float v1 = acc[i][j][2 * h + 1];
                s = fmaf(v0, v0, s);
                s = fmaf(v1, v1, s);
            }
            s += __shfl_xor_sync(0xffffffffu, s, 1);
            s += __shfl_xor_sync(0xffffffffu, s, 2);
            if (qcol == 0) nspart[m0 + i * 16 + h * 8 + qrow][nwarp] = s;
        }
    }
    __syncthreads();
    if (t < BM)
        g_npart[(size_t)bx * VP + gm + t] =
            nspart[t][0] + nspart[t][1] + nspart[t][2] + nspart[t][3];

    if (bx != by) {
        // --- col norm partials (slot by, rows gn..gn+127) ---
#pragma unroll
        for (int j = 0; j < 4; j++) {
#pragma unroll
            for (int c = 0; c < 2; c++) {
                float s = 0.f;
#pragma unroll
                for (int i = 0; i < 4; i++) {
                    float v0 = acc[i][j][c];
                    float v1 = acc[i][j][2 + c];
                    s = fmaf(v0, v0, s);
                    s = fmaf(v1, v1, s);
                }
                s += __shfl_xor_sync(0xffffffffu, s, 4);
                s += __shfl_xor_sync(0xffffffffu, s, 8);
                s += __shfl_xor_sync(0xffffffffu, s, 16);
                if (qrow == 0) cspart[n0 + j * 8 + qcol * 2 + c][mwarp] = s;
            }
        }
        __syncthreads();
        if (t < BM)
            g_npart[(size_t)by * VP + gn + t] = cspart[t][0] + cspart[t][1];
    } else {
        // diagonal block: zero diagonal entries (after norm partials!)
#pragma unroll
        for (int i = 0; i < 4; i++)
#pragma unroll
            for (int j = 0; j < 4; j++)
#pragma unroll
                for (int h = 0; h < 2; h++)
#pragma unroll
                    for (int c = 0; c < 2; c++) {
                        int r  = m0 + i * 16 + h * 8 + qrow;
                        int cc = n0 + j * 8 + qcol * 2 + c;
                        if (r == cc) acc[i][j][2 * h + c] = 0.f;
                    }
    }

    // --- store normal tile (bf16) ---
#pragma unroll
    for (int i = 0; i < 4; i++) {
        int row = gm + m0 + i * 16 + qrow;
#pragma unroll
        for (int j = 0; j < 4; j++) {
            int col = gn + n0 + j * 8 + qcol * 2;
            __nv_bfloat162 v0 = __floats2bfloat162_rn(acc[i][j][0], acc[i][j][1]);
            __nv_bfloat162 v1 = __floats2bfloat162_rn(acc[i][j][2], acc[i][j][3]);
            *(__nv_bfloat162*)&g_G[(size_t)row * VP + col]       = v0;
            *(__nv_bfloat162*)&g_G[(size_t)(row + 8) * VP + col] = v1;
        }
    }

    // --- transposed store via smem staging (stages are free now) ---
    if (bx != by) {
        float* staged = (float*)dyn;       // 32 x 132 fp32 = 16.9KB
#pragma unroll 1
        for (int ch = 0; ch < 4; ch++) {
            __syncthreads();
            if (nwarp == ch) {
#pragma unroll
                for (int j = 0; j < 4; j++)
#pragma unroll
                    for (int c = 0; c < 2; c++) {
                        int cl = j * 8 + qcol * 2 + c;
#pragma unroll
                        for (int i = 0; i < 4; i++)
#pragma unroll
                            for (int h = 0; h < 2; h++)
                                staged[cl * 132 + m0 + i * 16 + h * 8 + qrow] =
                                    acc[i][j][2 * h + c];
                    }
            }
            __syncthreads();
#pragma unroll
            for (int w = t; w < 512; w += 256) {
                int r  = w >> 4;
                int g8 = w & 15;
                float4 f0 = *(const float4*)&staged[r * 132 + g8 * 8];
                float4 f1 = *(const float4*)&staged[r * 132 + g8 * 8 + 4];
                __nv_bfloat162 h0 = __floats2bfloat162_rn(f0.x, f0.y);
                __nv_bfloat162 h1 = __floats2bfloat162_rn(f0.z, f0.w);
                __nv_bfloat162 h2 = __floats2bfloat162_rn(f1.x, f1.y);
                __nv_bfloat162 h3 = __floats2bfloat162_rn(f1.z, f1.w);
                uint4 pk;
                pk.x = *(unsigned*)&h0; pk.y = *(unsigned*)&h1;
                pk.z = *(unsigned*)&h2; pk.w = *(unsigned*)&h3;
                *(uint4*)&g_G[(size_t)(gn + ch * 32 + r) * VP + gm + g8 * 8] = pk;
            }
        }
    }
}

// ---------------------------------------------------------------------------
// Kernel 2: rinvh[r] = bf16(1/sqrt(sum of partials)); one warp per row.
// ---------------------------------------------------------------------------
__global__ void normfinish_kernel() {
    int w    = threadIdx.x >> 5;
    int lane = threadIdx.x & 31;
    int r    = blockIdx.x * 8 + w;
    if (r >= VP) return;
    float s = 0.f;
    if (lane < NBN) s = g_npart[(size_t)lane * VP + r];
#pragma unroll
    for (int o = 16; o > 0; o >>= 1) s += __shfl_xor_sync(0xffffffffu, s, o);
    if (lane == 0) {
        float ri = (r < VV) ? (1.f / sqrtf(s)) : 0.f;
        g_rinvh[r] = __float2bfloat16(ri);
    }
}

// ---------------------------------------------------------------------------
// Kernel 3: argmax — 4 rows/block, 128 threads, bulk-staged rows (32KB smem
// -> 7 CTAs/SM).  Scan math identical to R13/R15 -> identical map.
// ---------------------------------------------------------------------------
__global__ __launch_bounds__(128) void argmax_kernel() {
    extern __shared__ __align__(128) unsigned char am[];
    __nv_bfloat16* rows = (__nv_bfloat16*)am;                    // [4][VP]
    __nv_bfloat16* rs   = (__nv_bfloat16*)(am + AM_ROWS * ROWB); // [VP]
    __shared__ __align__(8) unsigned long long mbar[1];

    const int t = threadIdx.x;
    const int warp = t >> 5, lane = t & 31;
    const int row0 = blockIdx.x * AM_ROWS;
    const unsigned mb = smem_u32(&mbar[0]);

    if (t == 0) mbar_init(mb, 1);
    __syncthreads();
    if (t == 0) {
        mbar_expect_tx(mb, AM_ROWS * ROWB);
#pragma unroll
        for (int w = 0; w < AM_ROWS; w++)
            bulk_ld(smem_u32(rows) + w * ROWB,
                    &g_G[(size_t)(row0 + w) * VP], ROWB, mb);
    }
    // overlap: copy rinvh into smem while TMA is in flight
    for (int j = t; j < VP / 8; j += 128)
        ((uint4*)rs)[j] = ((const uint4*)g_rinvh)[j];
    mbar_wait(mb, 0);
    __syncthreads();

    const int row = row0 + warp;
    if (row >= VV) return;

    const uint4* __restrict__ G8 = (const uint4*)(rows + warp * VP);
    const uint4* __restrict__ R8 = (const uint4*)rs;
    __nv_bfloat16 best = __ushort_as_bfloat16(0xFF80);   // -inf
    int bk = lane;
#pragma unroll 4
    for (int k = lane; k < VP / 8; k += 32) {
        uint4 u = G8[k];
        uint4 rv = R8[k];
        __nv_bfloat162 p0 = __hmul2(*(__nv_bfloat162*)&u.x, *(__nv_bfloat162*)&rv.x);
        __nv_bfloat162 p1 = __hmul2(*(__nv_bfloat162*)&u.y, *(__nv_bfloat162*)&rv.y);
        __nv_bfloat162 p2 = __hmul2(*(__nv_bfloat162*)&u.z, *(__nv_bfloat162*)&rv.z);
        __nv_bfloat162 p3 = __hmul2(*(__nv_bfloat162*)&u.w, *(__nv_bfloat162*)&rv.w);
        __nv_bfloat162 mm = __hmax2(__hmax2(p0, p1), __hmax2(p2, p3));
        __nv_bfloat16 m = __hmax(__low2bfloat16(mm), __high2bfloat16(mm));
        if (__hgt(m, best)) { best = m; bk = k; }
    }
    // recover intra-vector index (descending scan => smallest c on ties)
    int bj = bk * 8;
    {
        uint4 u = G8[bk];
        uint4 rv = R8[bk];
        __nv_bfloat162 p[4];
        p[0] = __hmul2(*(__nv_bfloat162*)&u.x, *(__nv_bfloat162*)&rv.x);
        p[1] = __hmul2(*(__nv_bfloat162*)&u.y, *(__nv_bfloat162*)&rv.y);
        p[2] = __hmul2(*(__nv_bfloat162*)&u.z, *(__nv_bfloat162*)&rv.z);
        p[3] = __hmul2(*(__nv_bfloat162*)&u.w, *(__nv_bfloat162*)&rv.w);
#pragma unroll
        for (int c = 7; c >= 0; c--) {
            __nv_bfloat16 sc = (c & 1) ? __high2bfloat16(p[c >> 1])
                                       : __low2bfloat16(p[c >> 1]);
            if (__heq(sc, best)) bj = bk * 8 + c;
        }
    }
    float bestf = __bfloat162float(best);
#pragma unroll
    for (int o = 16; o > 0; o >>= 1) {
        float ob = __shfl_xor_sync(0xffffffffu, bestf, o);
        int   oj = __shfl_xor_sync(0xffffffffu, bj, o);
        if (ob > bestf || (ob == bestf && oj < bj)) { bestf = ob; bj = oj; }
    }
    if (lane == 0) g_map[row] = bj;
}

// ---------------------------------------------------------------------------
// Kernel 4: loss partials (MUFU-reduced softplus)  (R6/R10-proven)
// ---------------------------------------------------------------------------
__global__ void loss_kernel(const float* __restrict__ pred,
                            const float* __restrict__ label) {
    const int total4 = (BB * VV) / 4;
    const float4* __restrict__ pred4  = (const float4*)pred;
    const float4* __restrict__ label4 = (const float4*)label;

    float s1 = 0.f, s2 = 0.f;
    for (int i = blockIdx.x * blockDim.x + threadIdx.x; i < total4;
         i += gridDim.x * blockDim.x) {
        float4 p = pred4[i];
        float4 l = label4[i];
        s1 += fmaxf(p.x, 0.f) + fmaxf(p.y, 0.f) + fmaxf(p.z, 0.f) + fmaxf(p.w, 0.f);
        float prod = (1.f + __expf(-fabsf(p.x))) * (1.f + __expf(-fabsf(p.y))) *
                     (1.f + __expf(-fabsf(p.z))) * (1.f + __expf(-fabsf(p.w)));
        s1 += __logf(prod);
        if (l.x != 0.f || l.y != 0.f || l.z != 0.f || l.w != 0.f) {
            int base = i * 4;
#pragma unroll
            for (int c = 0; c < 4; c++) {
                float lv = (c == 0) ? l.x : (c == 1) ? l.y : (c == 2) ? l.z : l.w;
                if (lv != 0.f) {
                    int idx     = base + c;
                    int col     = idx % VV;
                    int row_off = idx - col;
                    s2 = fmaf(pred[row_off + g_map[col]], lv, s2);
                }
            }
        }
    }
    __shared__ float a[256], b[256];
    a[threadIdx.x] = s1;
    b[threadIdx.x] = s2;
    __syncthreads();
    for (int st = 128; st > 0; st >>= 1) {
        if (threadIdx.x < st) {
            a[threadIdx.x] += a[threadIdx.x + st];
            b[threadIdx.x] += b[threadIdx.x + st];
        }
        __syncthreads();
    }
    if (threadIdx.x == 0) {
        g_p1[blockIdx.x] = a[0];
        g_p2[blockIdx.x] = b[0];
    }
}

// ---------------------------------------------------------------------------
// Kernel 5: deterministic final reduction
// ---------------------------------------------------------------------------
__global__ void final_kernel(float* __restrict__ out) {
    __shared__ float a[256], b[256];
    float s1 = 0.f, s2 = 0.f;
    for (int i = threadIdx.x; i < NPART; i += 256) {
        s1 += g_p1[i];
        s2 += g_p2[i];
    }
    a[threadIdx.x] = s1;
    b[threadIdx.x] = s2;
    __syncthreads();
    for (int st = 128; st > 0; st >>= 1) {
        if (threadIdx.x < st) {
            a[threadIdx.x] += a[threadIdx.x + st];
            b[threadIdx.x] += b[threadIdx.x + st];
        }
        __syncthreads();
    }
    if (threadIdx.x == 0) out[0] = (a[0] - b[0]) / (float)BB;
}

// ---------------------------------------------------------------------------
extern "C" void kernel_launch(void* const* d_in, const int* in_sizes, int n_in,
                              void* d_out, int out_size) {
    const float* pred  = (const float*)d_in[0];   // [B, V]
    const float* label = (const float*)d_in[1];   // [B, V]
    const float* E     = (const float*)d_in[2];   // [V, D]
    float* out = (float*)d_out;

    cudaFuncSetAttribute(gram_kernel,
                         cudaFuncAttributeMaxDynamicSharedMemorySize, GRAM_SMEM);
    cudaFuncSetAttribute(argmax_kernel,
                         cudaFuncAttributeMaxDynamicSharedMemorySize, AM_SMEM);

    convert_kernel<<<(VP * 96 + 255) / 256, 256>>>(E);
    gram_kernel<<<NBLK, 256, GRAM_SMEM>>>();      // 325 upper-tri blocks
    normfinish_kernel<<<VP / 8, 256>>>();
    argmax_kernel<<<(VV + AM_ROWS - 1) / AM_ROWS, 128, AM_SMEM>>>();
    loss_kernel<<<NPART, 256>>>(pred, label);
    final_kernel<<<1, 256>>>(out);
}